// round 15
// baseline (speedup 1.0000x reference)
#include <cuda_runtime.h>
#include <math.h>

#define NT   1000
#define NTP  1024
#define H    128
#define B    1024
#define L    256
#define NTILE 16
#define NPAIR (NTILE*(NTILE+1)/2)   // 136 lower-triangle 64x64 tiles
#define NAUX  12
#define NBLK  (NPAIR + NAUX)        // 148 prep blocks (one wave)
#define NQ    ((B * L) / 4)         // 65536 quads
#define QAUX  ((NQ + NAUX - 1) / NAUX)   // 5462 quads per aux block
// W_out (517,3) row-major: rows 0:128 venue, 128:256 team, 256:384 opp,
// 384:512 result, 512 gf, 513 ga, 514:517 stats.

// ---- device scratch ----
__device__ float        g_G[NTP * NTP];
__device__ float4       g_PT1[NTP];
__device__ float4       g_PT2[NTP];
__device__ float4       g_PVR[9];
__device__ float        g_Gven[9];
__device__ unsigned int g_pidx[B * L];     // v | t<<2 | o<<12 | r<<22
__device__ float2       g_pgoals[B * L];   // (gf, ga)

// ---------------------------------------------------------------------------
// Kernel 1 (grid = 148):
//   blocks 0..135   : PURE gram tiles (f32x2 FMA, both k-halves preloaded)
//   blocks 136..147 : aux — proj (136-139), tables (140), + 1/12 pack each
//   All blocks signal PDL launch_dependents early.
// ---------------------------------------------------------------------------
__global__ void __launch_bounds__(256) prep_gram_kernel(
    const float* __restrict__ E,
    const float* __restrict__ venue_embed,
    const float* __restrict__ result_embed,
    const float* __restrict__ W,
    const int* __restrict__ venue, const int* __restrict__ team,
    const int* __restrict__ opp,   const int* __restrict__ result,
    const float* __restrict__ gf,  const float* __restrict__ ga) {
    const int bx  = blockIdx.x;
    const int tid = threadIdx.x;

    // let the main kernel launch and start its DRAM loads now
    asm volatile("griddepcontrol.launch_dependents;");

    if (bx < NPAIR) {
        __shared__ float As[64 * 68];
        __shared__ float Bs[64 * 68];
        const int ti = (int)floorf((sqrtf(8.0f * bx + 1.0f) - 1.0f) * 0.5f + 1e-4f);
        const int tj = bx - ti * (ti + 1) / 2;
        const int i0 = ti * 64;
        const int j0 = tj * 64;
        const int tx = tid & 15;
        const int ty = tid >> 4;

        // preload BOTH k-halves: 16 LDG.128 in flight
        float4 ra[2][4], rb[2][4];
        const float4 z4 = make_float4(0.f, 0.f, 0.f, 0.f);
        #pragma unroll
        for (int h = 0; h < 2; h++) {
            #pragma unroll
            for (int i = 0; i < 4; i++) {
                const int idx = tid + 256 * i;
                const int t  = idx >> 4;
                const int k4 = idx & 15;
                const int ri = i0 + t;
                const int rj = j0 + t;
                ra[h][i] = (ri < NT) ? *(const float4*)(E + ri * H + 64 * h + 4 * k4) : z4;
                rb[h][i] = (rj < NT) ? *(const float4*)(E + rj * H + 64 * h + 4 * k4) : z4;
            }
        }

        unsigned long long accp[4][2];
        #pragma unroll
        for (int u = 0; u < 4; u++) { accp[u][0] = 0ull; accp[u][1] = 0ull; }

        #pragma unroll
        for (int h = 0; h < 2; h++) {
            if (h) __syncthreads();
            #pragma unroll
            for (int i = 0; i < 4; i++) {
                const int idx = tid + 256 * i;
                const int t  = idx >> 4;
                const int k4 = idx & 15;
                const int c  = t ^ (4 * (k4 & 7));
                const int r0 = 4 * k4;
                As[(r0 + 0) * 68 + c] = ra[h][i].x;
                As[(r0 + 1) * 68 + c] = ra[h][i].y;
                As[(r0 + 2) * 68 + c] = ra[h][i].z;
                As[(r0 + 3) * 68 + c] = ra[h][i].w;
                Bs[(r0 + 0) * 68 + c] = rb[h][i].x;
                Bs[(r0 + 1) * 68 + c] = rb[h][i].y;
                Bs[(r0 + 2) * 68 + c] = rb[h][i].z;
                Bs[(r0 + 3) * 68 + c] = rb[h][i].w;
            }
            __syncthreads();

            #pragma unroll 16
            for (int k = 0; k < 64; k++) {
                const int cc = (k >> 2) & 7;
                const float4 a4 = *(const float4*)&As[k * 68 + 4 * (ty ^ cc)];
                const ulonglong2 b2 = *(const ulonglong2*)&Bs[k * 68 + 4 * (tx ^ cc)];
                const unsigned int au[4] = {
                    __float_as_uint(a4.x), __float_as_uint(a4.y),
                    __float_as_uint(a4.z), __float_as_uint(a4.w)};
                #pragma unroll
                for (int u = 0; u < 4; u++) {
                    unsigned long long ap;
                    asm("mov.b64 %0, {%1, %1};" : "=l"(ap) : "r"(au[u]));
                    asm("fma.rn.f32x2 %0, %1, %2, %0;"
                        : "+l"(accp[u][0]) : "l"(ap), "l"(b2.x));
                    asm("fma.rn.f32x2 %0, %1, %2, %0;"
                        : "+l"(accp[u][1]) : "l"(ap), "l"(b2.y));
                }
            }
        }

        float acc[4][4];
        #pragma unroll
        for (int u = 0; u < 4; u++) {
            unsigned int lo, hi;
            asm("mov.b64 {%0, %1}, %2;" : "=r"(lo), "=r"(hi) : "l"(accp[u][0]));
            acc[u][0] = __uint_as_float(lo); acc[u][1] = __uint_as_float(hi);
            asm("mov.b64 {%0, %1}, %2;" : "=r"(lo), "=r"(hi) : "l"(accp[u][1]));
            acc[u][2] = __uint_as_float(lo); acc[u][3] = __uint_as_float(hi);
        }

        float4* G4 = (float4*)g_G;
        #pragma unroll
        for (int u = 0; u < 4; u++) {
            const int i = i0 + 4 * ty + u;
            G4[(i * NTP + j0) / 4 + tx] =
                make_float4(acc[u][0], acc[u][1], acc[u][2], acc[u][3]);
        }
        if (ti != tj) {
            #pragma unroll
            for (int v = 0; v < 4; v++) {
                const int j = j0 + 4 * tx + v;
                G4[(j * NTP + i0) / 4 + ty] =
                    make_float4(acc[0][v], acc[1][v], acc[2][v], acc[3][v]);
            }
        }
        return;
    }

    // ---------------- aux blocks 136..147 ----------------
    const int aux = bx - NPAIR;    // 0..11

    // pack loads first (latency overlaps the work below)
    const int qbeg = aux * QAUX;
    const int qend = min(qbeg + QAUX, NQ);

    if (aux < 4) {
        const int t = aux * 256 + tid;
        if (t < NT) {
            const float4* row = (const float4*)(E + t * H);
            float a0 = 0, a1 = 0, a2 = 0, b0 = 0, b1 = 0, b2 = 0;
            #pragma unroll 8
            for (int k4 = 0; k4 < 32; k4++) {
                const float4 e = row[k4];
                const float ev[4] = {e.x, e.y, e.z, e.w};
                #pragma unroll
                for (int d = 0; d < 4; d++) {
                    const int k = 4 * k4 + d;
                    a0 += ev[d] * W[(128 + k) * 3 + 0];
                    a1 += ev[d] * W[(128 + k) * 3 + 1];
                    a2 += ev[d] * W[(128 + k) * 3 + 2];
                    b0 += ev[d] * W[(256 + k) * 3 + 0];
                    b1 += ev[d] * W[(256 + k) * 3 + 1];
                    b2 += ev[d] * W[(256 + k) * 3 + 2];
                }
            }
            g_PT1[t] = make_float4(a0, a1, a2, 0.0f);
            g_PT2[t] = make_float4(b0, b1, b2, 0.0f);
        }
    } else if (aux == 4) {
        const int w    = tid >> 5;
        const int lane = tid & 31;
        for (int p = w; p < 9; p += 8) {
            const int i = p / 3, j = p % 3;
            const float4 vi = *(const float4*)(venue_embed  + i * H + 4 * lane);
            const float4 vj = *(const float4*)(venue_embed  + j * H + 4 * lane);
            const float4 re = *(const float4*)(result_embed + j * H + 4 * lane);
            const float4 w0 = *(const float4*)(W + 12 * lane + 0);
            const float4 w1 = *(const float4*)(W + 12 * lane + 4);
            const float4 w2 = *(const float4*)(W + 12 * lane + 8);
            const float4 q0 = *(const float4*)(W + 384 * 3 + 12 * lane + 0);
            const float4 q1 = *(const float4*)(W + 384 * 3 + 12 * lane + 4);
            const float4 q2 = *(const float4*)(W + 384 * 3 + 12 * lane + 8);
            const float viv[4] = {vi.x, vi.y, vi.z, vi.w};
            const float vjv[4] = {vj.x, vj.y, vj.z, vj.w};
            const float rev[4] = {re.x, re.y, re.z, re.w};
            const float wv[12] = {w0.x, w0.y, w0.z, w0.w, w1.x, w1.y, w1.z, w1.w,
                                  w2.x, w2.y, w2.z, w2.w};
            const float qv[12] = {q0.x, q0.y, q0.z, q0.w, q1.x, q1.y, q1.z, q1.w,
                                  q2.x, q2.y, q2.z, q2.w};
            float gv = 0, p0 = 0, p1 = 0, p2 = 0;
            #pragma unroll
            for (int d = 0; d < 4; d++) {
                gv += viv[d] * vjv[d];
                p0 += viv[d] * wv[3 * d + 0] + rev[d] * qv[3 * d + 0];
                p1 += viv[d] * wv[3 * d + 1] + rev[d] * qv[3 * d + 1];
                p2 += viv[d] * wv[3 * d + 2] + rev[d] * qv[3 * d + 2];
            }
            #pragma unroll
            for (int off = 16; off; off >>= 1) {
                gv += __shfl_xor_sync(0xffffffffu, gv, off);
                p0 += __shfl_xor_sync(0xffffffffu, p0, off);
                p1 += __shfl_xor_sync(0xffffffffu, p1, off);
                p2 += __shfl_xor_sync(0xffffffffu, p2, off);
            }
            if (lane == 0) {
                g_Gven[p] = gv;
                g_PVR[p]  = make_float4(p0, p1, p2, 0.0f);
            }
        }
    }

    // ---- pack 1/12 of the stream data ----
    for (int q = qbeg + tid; q < qend; q += 256) {
        const int4   v4 = ((const int4*)venue)[q];
        const int4   t4 = ((const int4*)team)[q];
        const int4   o4 = ((const int4*)opp)[q];
        const int4   r4 = ((const int4*)result)[q];
        const float4 g4 = ((const float4*)gf)[q];
        const float4 a4 = ((const float4*)ga)[q];
        uint4 p;
        p.x = (unsigned)v4.x | ((unsigned)t4.x << 2) | ((unsigned)o4.x << 12) | ((unsigned)r4.x << 22);
        p.y = (unsigned)v4.y | ((unsigned)t4.y << 2) | ((unsigned)o4.y << 12) | ((unsigned)r4.y << 22);
        p.z = (unsigned)v4.z | ((unsigned)t4.z << 2) | ((unsigned)o4.z << 12) | ((unsigned)r4.z << 22);
        p.w = (unsigned)v4.w | ((unsigned)t4.w << 2) | ((unsigned)o4.w << 12) | ((unsigned)r4.w << 22);
        ((uint4*)g_pidx)[q] = p;
        ((float4*)g_pgoals)[2 * q]     = make_float4(g4.x, a4.x, g4.y, a4.y);
        ((float4*)g_pgoals)[2 * q + 1] = make_float4(g4.z, a4.z, g4.w, a4.w);
    }
}

// ---------------------------------------------------------------------------
// Kernel 2: main — PDL: pre-wait DRAM loads overlap prep; post-wait all L2.
// Dynamic smem (floats):
//   [0, 16384)       rows[8][2][1024]
//   [16384, 20480)   PT1s (1024 float4)
//   [20480, 24576)   PT2s (1024 float4)
//   [24576, 24612)   PVRs (9 float4)
//   [24612, 24621)   Gvens (9 float)
// ---------------------------------------------------------------------------
#define MAIN_SMEM_BYTES (24624 * 4)

__global__ void __launch_bounds__(256, 1) main_kernel(
    const float* __restrict__ stats,
    const int* __restrict__ next_venue, const int* __restrict__ next_team,
    const int* __restrict__ next_opp,
    const float* __restrict__ W, const float* __restrict__ b_out,
    float* __restrict__ out) {

    extern __shared__ float sm[];
    float*  rows  = sm;
    float4* PT1s  = (float4*)(sm + 16384);
    float4* PT2s  = (float4*)(sm + 20480);
    float4* PVRs  = (float4*)(sm + 24576);
    float*  Gvens = sm + 24612;

    const int tid  = threadIdx.x;
    const int lane = tid & 31;
    const int w    = tid >> 5;
    const int b    = blockIdx.x * 8 + w;

    // ---- pre-wait loads (raw inputs only; overlap prep compute) ----
    const int nv = next_venue[b];
    const int nt = next_team[b];
    const int no = next_opp[b];
    const float wgf0 = W[512 * 3 + 0], wgf1 = W[512 * 3 + 1], wgf2 = W[512 * 3 + 2];
    const float wga0 = W[513 * 3 + 0], wga1 = W[513 * 3 + 1], wga2 = W[513 * 3 + 2];
    float st0 = 0, st1 = 0, st2 = 0, bo0 = 0, bo1 = 0, bo2 = 0, ws[9];
    if (lane == 0) {
        st0 = stats[b * 3 + 0]; st1 = stats[b * 3 + 1]; st2 = stats[b * 3 + 2];
        bo0 = b_out[0]; bo1 = b_out[1]; bo2 = b_out[2];
        #pragma unroll
        for (int i = 0; i < 9; i++) ws[i] = W[514 * 3 + i];
    }

    // ---- wait for prep grid completion (memory visible after) ----
    asm volatile("griddepcontrol.wait;" ::: "memory");

    // ---- G rows into registers (L2) ----
    const float4* src1 = (const float4*)(g_G + nt * NTP);
    const float4* src2 = (const float4*)(g_G + no * NTP);
    float4 r1[8], r2[8];
    #pragma unroll
    for (int i = 0; i < 8; i++) {
        r1[i] = src1[lane + 32 * i];
        r2[i] = src2[lane + 32 * i];
    }

    // ---- packed streams (L2) ----
    const int q0 = b * 64 + lane;
    const int q1 = q0 + 32;
    const uint4  pa  = ((const uint4*)g_pidx)[q0];
    const uint4  pb  = ((const uint4*)g_pidx)[q1];
    const float4 ga0 = ((const float4*)g_pgoals)[2 * q0];
    const float4 ga1 = ((const float4*)g_pgoals)[2 * q0 + 1];
    const float4 gb0 = ((const float4*)g_pgoals)[2 * q1];
    const float4 gb1 = ((const float4*)g_pgoals)[2 * q1 + 1];

    // ---- cooperative table staging ----
    #pragma unroll
    for (int i = 0; i < 4; i++) {
        PT1s[tid + 256 * i] = g_PT1[tid + 256 * i];
        PT2s[tid + 256 * i] = g_PT2[tid + 256 * i];
    }
    if (tid < 9) { PVRs[tid] = g_PVR[tid]; Gvens[tid] = g_Gven[tid]; }
    __syncthreads();          // tables ready

    // ---- warp-private row staging ----
    float4* dst1 = (float4*)(rows + w * 2048);
    float4* dst2 = (float4*)(rows + w * 2048 + 1024);
    #pragma unroll
    for (int i = 0; i < 8; i++) {
        dst1[lane + 32 * i] = r1[i];
        dst2[lane + 32 * i] = r2[i];
    }
    __syncwarp();

    // ---- compute ----
    const unsigned int pp[8] = {pa.x, pa.y, pa.z, pa.w, pb.x, pb.y, pb.z, pb.w};
    int vv[8], tt[8], oo[8], rr[8];
    #pragma unroll
    for (int j = 0; j < 8; j++) {
        vv[j] = pp[j] & 3u;
        tt[j] = (pp[j] >> 2) & 1023u;
        oo[j] = (pp[j] >> 12) & 1023u;
        rr[j] = (pp[j] >> 22) & 3u;
    }
    const float gfv[8] = {ga0.x, ga0.z, ga1.x, ga1.z, gb0.x, gb0.z, gb1.x, gb1.z};
    const float gav[8] = {ga0.y, ga0.w, ga1.y, ga1.w, gb0.y, gb0.w, gb1.y, gb1.w};

    const float* rw0 = rows + w * 2048;
    const float* rw1 = rows + w * 2048 + 1024;

    const float inv_scale = 0.051031036307982884f;  // 1/sqrt(384)
    float s[8];
    #pragma unroll
    for (int j = 0; j < 8; j++)
        s[j] = (Gvens[vv[j] * 3 + nv] + rw0[tt[j]] + rw1[oo[j]]) * inv_scale;

    float m = s[0];
    #pragma unroll
    for (int j = 1; j < 8; j++) m = fmaxf(m, s[j]);
    #pragma unroll
    for (int off = 16; off; off >>= 1)
        m = fmaxf(m, __shfl_xor_sync(0xffffffffu, m, off));

    float e[8], su = 0.0f;
    #pragma unroll
    for (int j = 0; j < 8; j++) { e[j] = __expf(s[j] - m); su += e[j]; }
    #pragma unroll
    for (int off = 16; off; off >>= 1)
        su += __shfl_xor_sync(0xffffffffu, su, off);
    const float inv = __frcp_rn(su);

    float c0 = 0, c1 = 0, c2 = 0;
    #pragma unroll
    for (int j = 0; j < 8; j++) {
        const float a = e[j] * inv;
        const float4 p1  = PT1s[tt[j]];
        const float4 p2  = PT2s[oo[j]];
        const float4 pvr = PVRs[vv[j] * 3 + rr[j]];
        c0 += a * (p1.x + p2.x + pvr.x + gfv[j] * wgf0 + gav[j] * wga0);
        c1 += a * (p1.y + p2.y + pvr.y + gfv[j] * wgf1 + gav[j] * wga1);
        c2 += a * (p1.z + p2.z + pvr.z + gfv[j] * wgf2 + gav[j] * wga2);
    }
    #pragma unroll
    for (int off = 16; off; off >>= 1) {
        c0 += __shfl_xor_sync(0xffffffffu, c0, off);
        c1 += __shfl_xor_sync(0xffffffffu, c1, off);
        c2 += __shfl_xor_sync(0xffffffffu, c2, off);
    }

    if (lane == 0) {
        c0 += st0 * ws[0] + st1 * ws[3] + st2 * ws[6] + bo0;
        c1 += st0 * ws[1] + st1 * ws[4] + st2 * ws[7] + bo1;
        c2 += st0 * ws[2] + st1 * ws[5] + st2 * ws[8] + bo2;
        out[b * 3 + 0] = c0;
        out[b * 3 + 1] = c1;
        out[b * 3 + 2] = c2;
    }
}

// ---------------------------------------------------------------------------
extern "C" void kernel_launch(void* const* d_in, const int* in_sizes, int n_in,
                              void* d_out, int out_size) {
    const float* team_embed    = (const float*)d_in[0];
    const float* venue_embed   = (const float*)d_in[1];
    const float* result_embed  = (const float*)d_in[2];
    const float* W_out         = (const float*)d_in[3];
    const float* b_out         = (const float*)d_in[4];
    const float* goals_for     = (const float*)d_in[5];
    const float* goals_against = (const float*)d_in[6];
    const float* stats         = (const float*)d_in[7];
    const int*   venue         = (const int*)d_in[8];
    const int*   team          = (const int*)d_in[9];
    const int*   opponent      = (const int*)d_in[10];
    const int*   result        = (const int*)d_in[11];
    const int*   next_venue    = (const int*)d_in[12];
    const int*   next_team     = (const int*)d_in[13];
    const int*   next_opponent = (const int*)d_in[14];
    float* out = (float*)d_out;

    cudaFuncSetAttribute(main_kernel,
                         cudaFuncAttributeMaxDynamicSharedMemorySize,
                         MAIN_SMEM_BYTES);

    prep_gram_kernel<<<NBLK, 256>>>(team_embed, venue_embed,
                                    result_embed, W_out,
                                    venue, team, opponent, result,
                                    goals_for, goals_against);

    cudaLaunchConfig_t cfg = {};
    cfg.gridDim  = dim3(128, 1, 1);
    cfg.blockDim = dim3(256, 1, 1);
    cfg.dynamicSmemBytes = MAIN_SMEM_BYTES;
    cfg.stream = 0;
    cudaLaunchAttribute attr[1];
    attr[0].id = cudaLaunchAttributeProgrammaticStreamSerialization;
    attr[0].val.programmaticStreamSerializationAllowed = 1;
    cfg.attrs = attr;
    cfg.numAttrs = 1;
    cudaLaunchKernelEx(&cfg, main_kernel,
                       stats, next_venue, next_team, next_opponent,
                       W_out, b_out, out);
}

// round 16
// speedup vs baseline: 1.4365x; 1.4365x over previous
#include <cuda_runtime.h>
#include <math.h>

#define NT   1000
#define NTP  1024
#define H    128
#define B    1024
#define L    256
#define NTILE 16
#define NPAIR (NTILE*(NTILE+1)/2)   // 136 lower-triangle 64x64 tiles
#define NBLK (NPAIR + 5)            // 141 prep blocks
#define NQ   ((B * L) / 4)          // 65536 quads
#define QCHUNK ((NQ + NBLK - 1) / NBLK)   // 465
// W_out (517,3) row-major: rows 0:128 venue, 128:256 team, 256:384 opp,
// 384:512 result, 512 gf, 513 ga, 514:517 stats.

// ---- device scratch ----
__device__ float        g_G[NTP * NTP];
__device__ float4       g_PT1[NTP];
__device__ float4       g_PT2[NTP];
__device__ float4       g_PVR[9];
__device__ float        g_Gven[9];
__device__ unsigned int g_pidx[B * L];     // v | t<<2 | o<<12 | r<<22
__device__ float2       g_pgoals[B * L];   // (gf, ga)
__device__ unsigned int g_pnext[B];        // nv | nt<<2 | no<<12

// ---------------------------------------------------------------------------
// Kernel 1 (fused, grid = 141): R13-proven version + next packing.
//   blocks 0..135   : symmetric gram tiles (f32x2 FMA, both k-halves preloaded)
//   blocks 136..139 : team projections
//   block  140      : 3x3 tables + next_* packing
//   ALL blocks      : tail = pack 1/141 of the main-kernel stream data
// ---------------------------------------------------------------------------
__global__ void __launch_bounds__(256) prep_gram_kernel(
    const float* __restrict__ E,
    const float* __restrict__ venue_embed,
    const float* __restrict__ result_embed,
    const float* __restrict__ W,
    const int* __restrict__ venue, const int* __restrict__ team,
    const int* __restrict__ opp,   const int* __restrict__ result,
    const float* __restrict__ gf,  const float* __restrict__ ga,
    const int* __restrict__ next_venue, const int* __restrict__ next_team,
    const int* __restrict__ next_opp) {
    const int bx  = blockIdx.x;
    const int tid = threadIdx.x;

    if (bx < NPAIR) {
        __shared__ float As[64 * 68];
        __shared__ float Bs[64 * 68];
        const int ti = (int)floorf((sqrtf(8.0f * bx + 1.0f) - 1.0f) * 0.5f + 1e-4f);
        const int tj = bx - ti * (ti + 1) / 2;
        const int i0 = ti * 64;
        const int j0 = tj * 64;
        const int tx = tid & 15;
        const int ty = tid >> 4;

        // preload BOTH k-halves: 16 LDG.128 in flight
        float4 ra[2][4], rb[2][4];
        const float4 z4 = make_float4(0.f, 0.f, 0.f, 0.f);
        #pragma unroll
        for (int h = 0; h < 2; h++) {
            #pragma unroll
            for (int i = 0; i < 4; i++) {
                const int idx = tid + 256 * i;
                const int t  = idx >> 4;
                const int k4 = idx & 15;
                const int ri = i0 + t;
                const int rj = j0 + t;
                ra[h][i] = (ri < NT) ? *(const float4*)(E + ri * H + 64 * h + 4 * k4) : z4;
                rb[h][i] = (rj < NT) ? *(const float4*)(E + rj * H + 64 * h + 4 * k4) : z4;
            }
        }

        unsigned long long accp[4][2];
        #pragma unroll
        for (int u = 0; u < 4; u++) { accp[u][0] = 0ull; accp[u][1] = 0ull; }

        #pragma unroll
        for (int h = 0; h < 2; h++) {
            if (h) __syncthreads();
            #pragma unroll
            for (int i = 0; i < 4; i++) {
                const int idx = tid + 256 * i;
                const int t  = idx >> 4;
                const int k4 = idx & 15;
                const int c  = t ^ (4 * (k4 & 7));
                const int r0 = 4 * k4;
                As[(r0 + 0) * 68 + c] = ra[h][i].x;
                As[(r0 + 1) * 68 + c] = ra[h][i].y;
                As[(r0 + 2) * 68 + c] = ra[h][i].z;
                As[(r0 + 3) * 68 + c] = ra[h][i].w;
                Bs[(r0 + 0) * 68 + c] = rb[h][i].x;
                Bs[(r0 + 1) * 68 + c] = rb[h][i].y;
                Bs[(r0 + 2) * 68 + c] = rb[h][i].z;
                Bs[(r0 + 3) * 68 + c] = rb[h][i].w;
            }
            __syncthreads();

            #pragma unroll 16
            for (int k = 0; k < 64; k++) {
                const int cc = (k >> 2) & 7;
                const float4 a4 = *(const float4*)&As[k * 68 + 4 * (ty ^ cc)];
                const ulonglong2 b2 = *(const ulonglong2*)&Bs[k * 68 + 4 * (tx ^ cc)];
                const unsigned int au[4] = {
                    __float_as_uint(a4.x), __float_as_uint(a4.y),
                    __float_as_uint(a4.z), __float_as_uint(a4.w)};
                #pragma unroll
                for (int u = 0; u < 4; u++) {
                    unsigned long long ap;
                    asm("mov.b64 %0, {%1, %1};" : "=l"(ap) : "r"(au[u]));
                    asm("fma.rn.f32x2 %0, %1, %2, %0;"
                        : "+l"(accp[u][0]) : "l"(ap), "l"(b2.x));
                    asm("fma.rn.f32x2 %0, %1, %2, %0;"
                        : "+l"(accp[u][1]) : "l"(ap), "l"(b2.y));
                }
            }
        }

        float acc[4][4];
        #pragma unroll
        for (int u = 0; u < 4; u++) {
            unsigned int lo, hi;
            asm("mov.b64 {%0, %1}, %2;" : "=r"(lo), "=r"(hi) : "l"(accp[u][0]));
            acc[u][0] = __uint_as_float(lo); acc[u][1] = __uint_as_float(hi);
            asm("mov.b64 {%0, %1}, %2;" : "=r"(lo), "=r"(hi) : "l"(accp[u][1]));
            acc[u][2] = __uint_as_float(lo); acc[u][3] = __uint_as_float(hi);
        }

        float4* G4 = (float4*)g_G;
        #pragma unroll
        for (int u = 0; u < 4; u++) {
            const int i = i0 + 4 * ty + u;
            G4[(i * NTP + j0) / 4 + tx] =
                make_float4(acc[u][0], acc[u][1], acc[u][2], acc[u][3]);
        }
        if (ti != tj) {
            #pragma unroll
            for (int v = 0; v < 4; v++) {
                const int j = j0 + 4 * tx + v;
                G4[(j * NTP + i0) / 4 + ty] =
                    make_float4(acc[0][v], acc[1][v], acc[2][v], acc[3][v]);
            }
        }
    } else if (bx < NPAIR + 4) {
        const int t = (bx - NPAIR) * 256 + tid;
        if (t < NT) {
            const float4* row = (const float4*)(E + t * H);
            float a0 = 0, a1 = 0, a2 = 0, b0 = 0, b1 = 0, b2 = 0;
            #pragma unroll 8
            for (int k4 = 0; k4 < 32; k4++) {
                const float4 e = row[k4];
                const float ev[4] = {e.x, e.y, e.z, e.w};
                #pragma unroll
                for (int d = 0; d < 4; d++) {
                    const int k = 4 * k4 + d;
                    a0 += ev[d] * W[(128 + k) * 3 + 0];
                    a1 += ev[d] * W[(128 + k) * 3 + 1];
                    a2 += ev[d] * W[(128 + k) * 3 + 2];
                    b0 += ev[d] * W[(256 + k) * 3 + 0];
                    b1 += ev[d] * W[(256 + k) * 3 + 1];
                    b2 += ev[d] * W[(256 + k) * 3 + 2];
                }
            }
            g_PT1[t] = make_float4(a0, a1, a2, 0.0f);
            g_PT2[t] = make_float4(b0, b1, b2, 0.0f);
        }
    } else {
        // ---- pack next_* : one uint per batch (4 batches/thread) ----
        {
            const int4 nv4 = ((const int4*)next_venue)[tid];
            const int4 nt4 = ((const int4*)next_team)[tid];
            const int4 no4 = ((const int4*)next_opp)[tid];
            uint4 np;
            np.x = (unsigned)nv4.x | ((unsigned)nt4.x << 2) | ((unsigned)no4.x << 12);
            np.y = (unsigned)nv4.y | ((unsigned)nt4.y << 2) | ((unsigned)no4.y << 12);
            np.z = (unsigned)nv4.z | ((unsigned)nt4.z << 2) | ((unsigned)no4.z << 12);
            np.w = (unsigned)nv4.w | ((unsigned)nt4.w << 2) | ((unsigned)no4.w << 12);
            ((uint4*)g_pnext)[tid] = np;
        }
        // 3x3 tables: warp per (i,j)
        const int w    = tid >> 5;
        const int lane = tid & 31;
        for (int p = w; p < 9; p += 8) {
            const int i = p / 3, j = p % 3;
            const float4 vi = *(const float4*)(venue_embed  + i * H + 4 * lane);
            const float4 vj = *(const float4*)(venue_embed  + j * H + 4 * lane);
            const float4 re = *(const float4*)(result_embed + j * H + 4 * lane);
            const float4 w0 = *(const float4*)(W + 12 * lane + 0);
            const float4 w1 = *(const float4*)(W + 12 * lane + 4);
            const float4 w2 = *(const float4*)(W + 12 * lane + 8);
            const float4 q0 = *(const float4*)(W + 384 * 3 + 12 * lane + 0);
            const float4 q1 = *(const float4*)(W + 384 * 3 + 12 * lane + 4);
            const float4 q2 = *(const float4*)(W + 384 * 3 + 12 * lane + 8);
            const float viv[4] = {vi.x, vi.y, vi.z, vi.w};
            const float vjv[4] = {vj.x, vj.y, vj.z, vj.w};
            const float rev[4] = {re.x, re.y, re.z, re.w};
            const float wv[12] = {w0.x, w0.y, w0.z, w0.w, w1.x, w1.y, w1.z, w1.w,
                                  w2.x, w2.y, w2.z, w2.w};
            const float qv[12] = {q0.x, q0.y, q0.z, q0.w, q1.x, q1.y, q1.z, q1.w,
                                  q2.x, q2.y, q2.z, q2.w};
            float gv = 0, p0 = 0, p1 = 0, p2 = 0;
            #pragma unroll
            for (int d = 0; d < 4; d++) {
                gv += viv[d] * vjv[d];
                p0 += viv[d] * wv[3 * d + 0] + rev[d] * qv[3 * d + 0];
                p1 += viv[d] * wv[3 * d + 1] + rev[d] * qv[3 * d + 1];
                p2 += viv[d] * wv[3 * d + 2] + rev[d] * qv[3 * d + 2];
            }
            #pragma unroll
            for (int off = 16; off; off >>= 1) {
                gv += __shfl_xor_sync(0xffffffffu, gv, off);
                p0 += __shfl_xor_sync(0xffffffffu, p0, off);
                p1 += __shfl_xor_sync(0xffffffffu, p1, off);
                p2 += __shfl_xor_sync(0xffffffffu, p2, off);
            }
            if (lane == 0) {
                g_Gven[p] = gv;
                g_PVR[p]  = make_float4(p0, p1, p2, 0.0f);
            }
        }
    }

    // ---- tail: pack this block's slice of the stream data ----
    {
        const int qend = min((bx + 1) * QCHUNK, NQ);
        for (int q = bx * QCHUNK + tid; q < qend; q += 256) {
            const int4   v4 = ((const int4*)venue)[q];
            const int4   t4 = ((const int4*)team)[q];
            const int4   o4 = ((const int4*)opp)[q];
            const int4   r4 = ((const int4*)result)[q];
            const float4 g4 = ((const float4*)gf)[q];
            const float4 a4 = ((const float4*)ga)[q];
            uint4 p;
            p.x = (unsigned)v4.x | ((unsigned)t4.x << 2) | ((unsigned)o4.x << 12) | ((unsigned)r4.x << 22);
            p.y = (unsigned)v4.y | ((unsigned)t4.y << 2) | ((unsigned)o4.y << 12) | ((unsigned)r4.y << 22);
            p.z = (unsigned)v4.z | ((unsigned)t4.z << 2) | ((unsigned)o4.z << 12) | ((unsigned)r4.z << 22);
            p.w = (unsigned)v4.w | ((unsigned)t4.w << 2) | ((unsigned)o4.w << 12) | ((unsigned)r4.w << 22);
            ((uint4*)g_pidx)[q] = p;
            ((float4*)g_pgoals)[2 * q]     = make_float4(g4.x, a4.x, g4.y, a4.y);
            ((float4*)g_pgoals)[2 * q + 1] = make_float4(g4.z, a4.z, g4.w, a4.w);
        }
    }
}

// ---------------------------------------------------------------------------
// Kernel 2: main — warp per batch, single packed chain-head load.
// Dynamic smem (floats):
//   [0, 16384)       rows[8][2][1024]
//   [16384, 20480)   PT1s (1024 float4)
//   [20480, 24576)   PT2s (1024 float4)
//   [24576, 24612)   PVRs (9 float4)
//   [24612, 24621)   Gvens (9 float)
// ---------------------------------------------------------------------------
#define MAIN_SMEM_BYTES (24624 * 4)

__global__ void __launch_bounds__(256, 1) main_kernel(
    const float* __restrict__ stats,
    const float* __restrict__ W, const float* __restrict__ b_out,
    float* __restrict__ out) {

    extern __shared__ float sm[];
    float*  rows  = sm;
    float4* PT1s  = (float4*)(sm + 16384);
    float4* PT2s  = (float4*)(sm + 20480);
    float4* PVRs  = (float4*)(sm + 24576);
    float*  Gvens = sm + 24612;

    const int tid  = threadIdx.x;
    const int lane = tid & 31;
    const int w    = tid >> 5;
    const int b    = blockIdx.x * 8 + w;

    // ---- 1. chain head: ONE packed L2-hot load ----
    const unsigned int np = g_pnext[b];
    const int nv = np & 3u;
    const int nt = (np >> 2) & 1023u;
    const int no = (np >> 12) & 1023u;

    // ---- 2. dependent: G rows into REGISTERS (16 LDG.128 in flight) ----
    const float4* src1 = (const float4*)(g_G + nt * NTP);
    const float4* src2 = (const float4*)(g_G + no * NTP);
    float4 r1[8], r2[8];
    #pragma unroll
    for (int i = 0; i < 8; i++) {
        r1[i] = src1[lane + 32 * i];
        r2[i] = src2[lane + 32 * i];
    }

    // ---- 3. independent: packed streams ----
    const int q0 = b * 64 + lane;
    const int q1 = q0 + 32;
    const uint4  pa  = ((const uint4*)g_pidx)[q0];
    const uint4  pb  = ((const uint4*)g_pidx)[q1];
    const float4 ga0 = ((const float4*)g_pgoals)[2 * q0];
    const float4 ga1 = ((const float4*)g_pgoals)[2 * q0 + 1];
    const float4 gb0 = ((const float4*)g_pgoals)[2 * q1];
    const float4 gb1 = ((const float4*)g_pgoals)[2 * q1 + 1];

    // ---- 4. epilogue scalars ----
    const float wgf0 = W[512 * 3 + 0], wgf1 = W[512 * 3 + 1], wgf2 = W[512 * 3 + 2];
    const float wga0 = W[513 * 3 + 0], wga1 = W[513 * 3 + 1], wga2 = W[513 * 3 + 2];
    float st0 = 0, st1 = 0, st2 = 0, bo0 = 0, bo1 = 0, bo2 = 0, ws[9];
    if (lane == 0) {
        st0 = stats[b * 3 + 0]; st1 = stats[b * 3 + 1]; st2 = stats[b * 3 + 2];
        bo0 = b_out[0]; bo1 = b_out[1]; bo2 = b_out[2];
        #pragma unroll
        for (int i = 0; i < 9; i++) ws[i] = W[514 * 3 + i];
    }

    // ---- 5. cooperative table staging ----
    #pragma unroll
    for (int i = 0; i < 4; i++) {
        PT1s[tid + 256 * i] = g_PT1[tid + 256 * i];
        PT2s[tid + 256 * i] = g_PT2[tid + 256 * i];
    }
    if (tid < 9) { PVRs[tid] = g_PVR[tid]; Gvens[tid] = g_Gven[tid]; }
    __syncthreads();          // tables ready (does NOT wait on row staging)

    // ---- 6. warp-private row staging ----
    float4* dst1 = (float4*)(rows + w * 2048);
    float4* dst2 = (float4*)(rows + w * 2048 + 1024);
    #pragma unroll
    for (int i = 0; i < 8; i++) {
        dst1[lane + 32 * i] = r1[i];
        dst2[lane + 32 * i] = r2[i];
    }
    __syncwarp();

    // ---- 7. compute ----
    const unsigned int pp[8] = {pa.x, pa.y, pa.z, pa.w, pb.x, pb.y, pb.z, pb.w};
    int vv[8], tt[8], oo[8], rr[8];
    #pragma unroll
    for (int j = 0; j < 8; j++) {
        vv[j] = pp[j] & 3u;
        tt[j] = (pp[j] >> 2) & 1023u;
        oo[j] = (pp[j] >> 12) & 1023u;
        rr[j] = (pp[j] >> 22) & 3u;
    }
    const float gfv[8] = {ga0.x, ga0.z, ga1.x, ga1.z, gb0.x, gb0.z, gb1.x, gb1.z};
    const float gav[8] = {ga0.y, ga0.w, ga1.y, ga1.w, gb0.y, gb0.w, gb1.y, gb1.w};

    const float* rw0 = rows + w * 2048;
    const float* rw1 = rows + w * 2048 + 1024;

    const float inv_scale = 0.051031036307982884f;  // 1/sqrt(384)
    float s[8];
    #pragma unroll
    for (int j = 0; j < 8; j++)
        s[j] = (Gvens[vv[j] * 3 + nv] + rw0[tt[j]] + rw1[oo[j]]) * inv_scale;

    float m = s[0];
    #pragma unroll
    for (int j = 1; j < 8; j++) m = fmaxf(m, s[j]);
    #pragma unroll
    for (int off = 16; off; off >>= 1)
        m = fmaxf(m, __shfl_xor_sync(0xffffffffu, m, off));

    float e[8], su = 0.0f;
    #pragma unroll
    for (int j = 0; j < 8; j++) { e[j] = __expf(s[j] - m); su += e[j]; }
    #pragma unroll
    for (int off = 16; off; off >>= 1)
        su += __shfl_xor_sync(0xffffffffu, su, off);
    const float inv = __frcp_rn(su);

    float c0 = 0, c1 = 0, c2 = 0;
    #pragma unroll
    for (int j = 0; j < 8; j++) {
        const float a = e[j] * inv;
        const float4 p1  = PT1s[tt[j]];
        const float4 p2  = PT2s[oo[j]];
        const float4 pvr = PVRs[vv[j] * 3 + rr[j]];
        c0 += a * (p1.x + p2.x + pvr.x + gfv[j] * wgf0 + gav[j] * wga0);
        c1 += a * (p1.y + p2.y + pvr.y + gfv[j] * wgf1 + gav[j] * wga1);
        c2 += a * (p1.z + p2.z + pvr.z + gfv[j] * wgf2 + gav[j] * wga2);
    }
    #pragma unroll
    for (int off = 16; off; off >>= 1) {
        c0 += __shfl_xor_sync(0xffffffffu, c0, off);
        c1 += __shfl_xor_sync(0xffffffffu, c1, off);
        c2 += __shfl_xor_sync(0xffffffffu, c2, off);
    }

    if (lane == 0) {
        c0 += st0 * ws[0] + st1 * ws[3] + st2 * ws[6] + bo0;
        c1 += st0 * ws[1] + st1 * ws[4] + st2 * ws[7] + bo1;
        c2 += st0 * ws[2] + st1 * ws[5] + st2 * ws[8] + bo2;
        out[b * 3 + 0] = c0;
        out[b * 3 + 1] = c1;
        out[b * 3 + 2] = c2;
    }
}

// ---------------------------------------------------------------------------
extern "C" void kernel_launch(void* const* d_in, const int* in_sizes, int n_in,
                              void* d_out, int out_size) {
    const float* team_embed    = (const float*)d_in[0];
    const float* venue_embed   = (const float*)d_in[1];
    const float* result_embed  = (const float*)d_in[2];
    const float* W_out         = (const float*)d_in[3];
    const float* b_out         = (const float*)d_in[4];
    const float* goals_for     = (const float*)d_in[5];
    const float* goals_against = (const float*)d_in[6];
    const float* stats         = (const float*)d_in[7];
    const int*   venue         = (const int*)d_in[8];
    const int*   team          = (const int*)d_in[9];
    const int*   opponent      = (const int*)d_in[10];
    const int*   result        = (const int*)d_in[11];
    const int*   next_venue    = (const int*)d_in[12];
    const int*   next_team     = (const int*)d_in[13];
    const int*   next_opponent = (const int*)d_in[14];
    float* out = (float*)d_out;

    cudaFuncSetAttribute(main_kernel,
                         cudaFuncAttributeMaxDynamicSharedMemorySize,
                         MAIN_SMEM_BYTES);

    prep_gram_kernel<<<NBLK, 256>>>(team_embed, venue_embed,
                                    result_embed, W_out,
                                    venue, team, opponent, result,
                                    goals_for, goals_against,
                                    next_venue, next_team, next_opponent);

    main_kernel<<<128, 256, MAIN_SMEM_BYTES>>>(
        stats, W_out, b_out, out);
}